// round 1
// baseline (speedup 1.0000x reference)
#include <cuda_runtime.h>
#include <cuda_bf16.h>
#include <cstdint>
#include <cfloat>

// Problem constants
#define B_    64
#define H_    512
#define N_    16384
#define K_    4
#define W_    64
#define DIN_  512
#define KDIM_ 1088           // DIN + W + H
#define G4_   2048           // 4*H

// d_out layout (floats): y(32768) h(32768) c(32768) M(67108864) wr(1048576) usage(1048576) r(4096)
#define OFF_Y   0
#define OFF_H   32768
#define OFF_C   65536
#define OFF_M   98304
#define OFF_WR  67207168
#define OFF_US  68255744
#define OFF_R   69304320

// scratch (static device globals; no allocation allowed)
__device__ float g_z[B_ * G4_];
__device__ float g_params[B_ * 194];
__device__ float g_qn[B_ * W_];
__device__ float g_a[B_ * W_];
__device__ float g_e[B_ * W_];
__device__ float g_alpha[B_];
__device__ float g_gamma[B_];
__device__ int   g_lru[B_];
__device__ float g_sim[B_ * N_];

__device__ __forceinline__ float sigmoidf_(float x) { return 1.0f / (1.0f + expf(-x)); }

// ---------------------------------------------------------------------------
// K1: z = [inputs, r_prev, h_prev] @ [Wk; Uk]   (64 x 2048, K=1088)
// grid = 64 (j-tiles of 32), block = 256
// ---------------------------------------------------------------------------
__global__ void k_gemm_z(const float* __restrict__ inp, const float* __restrict__ rprev,
                         const float* __restrict__ hprev, const float* __restrict__ Wk,
                         const float* __restrict__ Uk) {
    __shared__ float Xs[64][33];
    __shared__ float Ws[32][33];
    const int j0  = blockIdx.x * 32;
    const int tid = threadIdx.x;
    const int jj  = tid & 31;
    const int bb  = tid >> 5;   // 0..7

    float acc[8];
#pragma unroll
    for (int r = 0; r < 8; r++) acc[r] = 0.0f;

    for (int k0 = 0; k0 < KDIM_; k0 += 32) {
        for (int idx = tid; idx < 64 * 32; idx += 256) {
            int b = idx >> 5, kk = idx & 31, k = k0 + kk;
            float v;
            if (k < DIN_)            v = inp[b * DIN_ + k];
            else if (k < DIN_ + W_)  v = rprev[b * W_ + (k - DIN_)];
            else                     v = hprev[b * H_ + (k - DIN_ - W_)];
            Xs[b][kk] = v;
        }
        for (int idx = tid; idx < 32 * 32; idx += 256) {
            int kk = idx >> 5, jx = idx & 31, k = k0 + kk;
            float w = (k < DIN_ + W_) ? Wk[k * G4_ + j0 + jx]
                                      : Uk[(k - DIN_ - W_) * G4_ + j0 + jx];
            Ws[kk][jx] = w;
        }
        __syncthreads();
#pragma unroll
        for (int kk = 0; kk < 32; kk++) {
            float w = Ws[kk][jj];
#pragma unroll
            for (int r = 0; r < 8; r++) acc[r] += Xs[bb * 8 + r][kk] * w;
        }
        __syncthreads();
    }
#pragma unroll
    for (int r = 0; r < 8; r++) g_z[(bb * 8 + r) * G4_ + j0 + jj] = acc[r];
}

// ---------------------------------------------------------------------------
// K2: gates -> h_curr, c_curr
// ---------------------------------------------------------------------------
__global__ void k_gates(const float* __restrict__ cprev, const float* __restrict__ bl,
                        float* __restrict__ h_out, float* __restrict__ c_out) {
    int idx = blockIdx.x * blockDim.x + threadIdx.x;
    if (idx >= B_ * H_) return;
    int b = idx >> 9, hh = idx & 511;
    const float* zb = g_z + b * G4_;
    float zi = zb[hh]            + bl[hh];
    float zf = zb[H_ + hh]       + bl[H_ + hh];
    float zg = zb[2 * H_ + hh]   + bl[2 * H_ + hh];
    float zo = zb[3 * H_ + hh]   + bl[3 * H_ + hh];
    float ig = sigmoidf_(zi);
    float fg = sigmoidf_(zf);
    float og = sigmoidf_(zo);
    float c  = fg * cprev[idx] + ig * tanhf(zg);
    c_out[idx] = c;
    h_out[idx] = og * tanhf(c);
}

// ---------------------------------------------------------------------------
// K3a: params = h @ Wp + bp    grid=194 (j), block=64 (b)
// ---------------------------------------------------------------------------
__global__ void k_params(const float* __restrict__ h, const float* __restrict__ Wp,
                         const float* __restrict__ bp) {
    int j = blockIdx.x;
    int b = threadIdx.x;
    float acc = 0.0f;
    for (int k = 0; k < H_; k++) acc += h[b * H_ + k] * Wp[k * 194 + j];
    g_params[b * 194 + j] = acc + bp[j];
}

// ---------------------------------------------------------------------------
// K3b: derived per-b quantities: qn (l2norm), a, e=sig, alpha, gamma
// grid=64 (b), block=64 (w)
// ---------------------------------------------------------------------------
__global__ void k_derive() {
    int b = blockIdx.x, w = threadIdx.x;
    const float* p = g_params + b * 194;
    float q = p[w];
    float s = q * q;
#pragma unroll
    for (int off = 16; off > 0; off >>= 1) s += __shfl_down_sync(0xffffffffu, s, off);
    __shared__ float ws[2];
    if ((w & 31) == 0) ws[w >> 5] = s;
    __syncthreads();
    float tot = ws[0] + ws[1];
    g_qn[b * W_ + w] = q * rsqrtf(fmaxf(tot, 1e-12f));
    g_a[b * W_ + w]  = p[W_ + w];
    g_e[b * W_ + w]  = sigmoidf_(p[2 * W_ + w]);
    if (w == 0) {
        g_alpha[b] = sigmoidf_(p[192]);
        g_gamma[b] = sigmoidf_(p[193]);
    }
}

// ---------------------------------------------------------------------------
// K4: sim[b,n] = dot(qn[b], l2norm(M[b,n]))
// one warp per 64-float row; block=256 (8 warps); grid = B*N/8
// ---------------------------------------------------------------------------
__global__ void k_sim(const float* __restrict__ M) {
    int warp = threadIdx.x >> 5, lane = threadIdx.x & 31;
    size_t row = (size_t)blockIdx.x * 8 + warp;
    int b = (int)(row >> 14);
    const float2 m = ((const float2*)(M + row * 64))[lane];
    const float2 q = ((const float2*)(g_qn + b * W_))[lane];
    float dot = m.x * q.x + m.y * q.y;
    float ss  = m.x * m.x + m.y * m.y;
#pragma unroll
    for (int off = 16; off > 0; off >>= 1) {
        dot += __shfl_down_sync(0xffffffffu, dot, off);
        ss  += __shfl_down_sync(0xffffffffu, ss,  off);
    }
    if (lane == 0) g_sim[row] = dot * rsqrtf(fmaxf(ss, 1e-12f));
}

// ---------------------------------------------------------------------------
// K5: per-b: top-4 select + sparse softmax -> w_r, usage_curr, lru argmax, r_curr
// grid=64 (b), block=256
// ---------------------------------------------------------------------------
__global__ void k_select(const float* __restrict__ Mprev, const float* __restrict__ usprev,
                         float* __restrict__ wr_out, float* __restrict__ us_out,
                         float* __restrict__ r_out) {
    const int b = blockIdx.x, tid = threadIdx.x;
    __shared__ float sv[256][4];
    __shared__ int   si[256][4];
    __shared__ int   s_idx4[4];
    __shared__ float s_p4[4];

    // ---- phase A: local top-4 (sorted: value desc, index asc on ties) ----
    float lv[4]; int li[4];
#pragma unroll
    for (int j = 0; j < 4; j++) { lv[j] = -FLT_MAX; li[j] = 0x7FFFFFFF; }
    const float* simb = g_sim + b * N_;
    for (int n = tid; n < N_; n += 256) {
        float v = simb[n];
        if (v > lv[3]) {                      // strict: ties keep earlier (lower) index
            lv[3] = v; li[3] = n;
#pragma unroll
            for (int p = 3; p > 0; p--) {
                bool up = (lv[p] > lv[p-1]) || (lv[p] == lv[p-1] && li[p] < li[p-1]);
                if (up) {
                    float tv = lv[p]; lv[p] = lv[p-1]; lv[p-1] = tv;
                    int   ti = li[p]; li[p] = li[p-1]; li[p-1] = ti;
                }
            }
        }
    }
#pragma unroll
    for (int j = 0; j < 4; j++) { sv[tid][j] = lv[j]; si[tid][j] = li[j]; }
    __syncthreads();

    // tree merge of sorted 4-lists
    for (int s = 128; s > 0; s >>= 1) {
        if (tid < s) {
            float av[4], bv[4], ov[4]; int ai[4], bi[4], oi[4];
#pragma unroll
            for (int j = 0; j < 4; j++) {
                av[j] = sv[tid][j];     ai[j] = si[tid][j];
                bv[j] = sv[tid + s][j]; bi[j] = si[tid + s][j];
            }
            int pa = 0, pb = 0;
            for (int t = 0; t < 4; t++) {
                bool ta = (av[pa] > bv[pb]) || (av[pa] == bv[pb] && ai[pa] < bi[pb]);
                if (ta) { ov[t] = av[pa]; oi[t] = ai[pa]; pa++; }
                else    { ov[t] = bv[pb]; oi[t] = bi[pb]; pb++; }
            }
#pragma unroll
            for (int j = 0; j < 4; j++) { sv[tid][j] = ov[j]; si[tid][j] = oi[j]; }
        }
        __syncthreads();
    }

    if (tid == 0) {
        float vmax = sv[0][0];
        float sum = 0.0f;
        float ev[4];
#pragma unroll
        for (int j = 0; j < 4; j++) { ev[j] = expf(sv[0][j] - vmax); sum += ev[j]; }
        float inv = 1.0f / sum;
#pragma unroll
        for (int j = 0; j < 4; j++) { s_p4[j] = ev[j] * inv; s_idx4[j] = si[0][j]; }
    }
    __syncthreads();

    // ---- phase B: write w_r + usage, track argmax(usage) ----
    const int i0 = s_idx4[0], i1 = s_idx4[1], i2 = s_idx4[2], i3 = s_idx4[3];
    const float p0 = s_p4[0], p1 = s_p4[1], p2 = s_p4[2], p3 = s_p4[3];
    float bm = -FLT_MAX; int bi = 0x7FFFFFFF;
    for (int n = tid; n < N_; n += 256) {
        float wr = 0.0f; bool hit = false;
        if (n == i0) { wr = p0; hit = true; }
        if (n == i1) { wr = p1; hit = true; }
        if (n == i2) { wr = p2; hit = true; }
        if (n == i3) { wr = p3; hit = true; }
        wr_out[b * N_ + n] = wr;
        float u = hit ? 0.0f : usprev[b * N_ + n] + 1.0f;
        us_out[b * N_ + n] = u;
        if (u > bm || (u == bm && n < bi)) { bm = u; bi = n; }
    }
    __syncthreads();
    sv[tid][0] = bm; si[tid][0] = bi;
    __syncthreads();
    for (int s = 128; s > 0; s >>= 1) {
        if (tid < s) {
            float ov = sv[tid + s][0]; int oi = si[tid + s][0];
            if (ov > sv[tid][0] || (ov == sv[tid][0] && oi < si[tid][0])) {
                sv[tid][0] = ov; si[tid][0] = oi;
            }
        }
        __syncthreads();
    }
    if (tid == 0) g_lru[b] = si[0][0];

    // ---- phase C: r_curr = sum_j p_j * M[b, idx_j, :] ----
    if (tid < W_) {
        float r = p0 * Mprev[((size_t)b * N_ + i0) * W_ + tid]
                + p1 * Mprev[((size_t)b * N_ + i1) * W_ + tid]
                + p2 * Mprev[((size_t)b * N_ + i2) * W_ + tid]
                + p3 * Mprev[((size_t)b * N_ + i3) * W_ + tid];
        r_out[b * W_ + tid] = r;
    }
}

// ---------------------------------------------------------------------------
// K6: M_curr = M_prev*(1 - ww*e) + ww*a,  ww = alpha*(gamma*wr_prev + (1-gamma)*I_lru)
// grid = B*128 (each block: 128 rows of one b), block=256, float4
// ---------------------------------------------------------------------------
__global__ void k_update(const float* __restrict__ Mprev, const float* __restrict__ wrprev,
                         float* __restrict__ Mout) {
    const int b = blockIdx.x >> 7;
    const int chunk = blockIdx.x & 127;
    const int tid = threadIdx.x;
    __shared__ float se[W_], sa[W_];
    __shared__ float s_alpha, s_gamma;
    __shared__ int s_lru;
    if (tid < W_) { se[tid] = g_e[b * W_ + tid]; sa[tid] = g_a[b * W_ + tid]; }
    if (tid == 0) { s_alpha = g_alpha[b]; s_gamma = g_gamma[b]; s_lru = g_lru[b]; }
    __syncthreads();

    const int n0 = chunk * 128;
    const float4* Mi = (const float4*)(Mprev + ((size_t)b * N_ + n0) * W_);
    float4* Mo = (float4*)(Mout + ((size_t)b * N_ + n0) * W_);
    const float alpha = s_alpha, gamma = s_gamma;
    const int lru = s_lru;

#pragma unroll
    for (int it = 0; it < 8; it++) {
        int flat = it * 256 + tid;       // 0..2047 float4s
        int nl = flat >> 4;              // row within chunk
        int w4 = flat & 15;
        int n = n0 + nl;
        float wr = wrprev[b * N_ + n];
        float ww = alpha * (gamma * wr + (1.0f - gamma) * ((n == lru) ? 1.0f : 0.0f));
        float4 m = Mi[flat];
        float e0 = se[w4 * 4 + 0], e1 = se[w4 * 4 + 1], e2 = se[w4 * 4 + 2], e3 = se[w4 * 4 + 3];
        float a0 = sa[w4 * 4 + 0], a1 = sa[w4 * 4 + 1], a2 = sa[w4 * 4 + 2], a3 = sa[w4 * 4 + 3];
        float4 o;
        o.x = m.x * (1.0f - ww * e0) + ww * a0;
        o.y = m.y * (1.0f - ww * e1) + ww * a1;
        o.z = m.z * (1.0f - ww * e2) + ww * a2;
        o.w = m.w * (1.0f - ww * e3) + ww * a3;
        Mo[flat] = o;
    }
}

// ---------------------------------------------------------------------------
// K7: y_out = [h_curr, r_curr] @ Wf + bf   grid=512 (j), block=64 (b)
// ---------------------------------------------------------------------------
__global__ void k_yout(const float* __restrict__ h, const float* __restrict__ r,
                       const float* __restrict__ Wf, const float* __restrict__ bf,
                       float* __restrict__ y) {
    int j = blockIdx.x;
    int b = threadIdx.x;
    float acc = bf[j];
    for (int k = 0; k < H_; k++)  acc += h[b * H_ + k] * Wf[k * H_ + j];
    for (int k = 0; k < W_; k++)  acc += r[b * W_ + k] * Wf[(H_ + k) * H_ + j];
    y[b * H_ + j] = acc;
}

// ---------------------------------------------------------------------------
extern "C" void kernel_launch(void* const* d_in, const int* in_sizes, int n_in,
                              void* d_out, int out_size) {
    const float* inputs = (const float*)d_in[0];
    const float* h_prev = (const float*)d_in[1];
    const float* c_prev = (const float*)d_in[2];
    const float* M_prev = (const float*)d_in[3];
    const float* wr_prev = (const float*)d_in[4];
    const float* usage_prev = (const float*)d_in[5];
    const float* r_prev = (const float*)d_in[6];
    const float* Wk = (const float*)d_in[7];
    const float* Uk = (const float*)d_in[8];
    const float* b_lstm = (const float*)d_in[9];
    const float* Wp = (const float*)d_in[10];
    const float* bp = (const float*)d_in[11];
    const float* Wf = (const float*)d_in[12];
    const float* bf = (const float*)d_in[13];

    float* out = (float*)d_out;
    float* o_y  = out + OFF_Y;
    float* o_h  = out + OFF_H;
    float* o_c  = out + OFF_C;
    float* o_M  = out + OFF_M;
    float* o_wr = out + OFF_WR;
    float* o_us = out + OFF_US;
    float* o_r  = out + OFF_R;

    k_gemm_z<<<64, 256>>>(inputs, r_prev, h_prev, Wk, Uk);
    k_gates<<<(B_ * H_ + 255) / 256, 256>>>(c_prev, b_lstm, o_h, o_c);
    k_params<<<194, 64>>>(o_h, Wp, bp);
    k_derive<<<64, 64>>>();
    k_sim<<<(B_ * N_) / 8, 256>>>(M_prev);
    k_select<<<64, 256>>>(M_prev, usage_prev, o_wr, o_us, o_r);
    k_update<<<B_ * 128, 256>>>(M_prev, wr_prev, o_M);
    k_yout<<<512, 64>>>(o_h, o_r, Wf, bf, o_y);
}

// round 2
// speedup vs baseline: 2.7584x; 2.7584x over previous
#include <cuda_runtime.h>
#include <cuda_bf16.h>
#include <cstdint>
#include <cfloat>

#define B_    64
#define H_    512
#define N_    16384
#define K_    4
#define W_    64
#define DIN_  512
#define KDIM_ 1088
#define G4_   2048
#define KSPLIT_ 8
#define KPER_   136   // 1088/8

// d_out layout (floats)
#define OFF_Y   0
#define OFF_H   32768
#define OFF_C   65536
#define OFF_M   98304
#define OFF_WR  67207168
#define OFF_US  68255744
#define OFF_R   69304320

// scratch
__device__ float g_zp[KSPLIT_ * B_ * G4_];     // 4MB GEMM partials
__device__ float g_params[B_ * 194];
__device__ float g_qn[B_ * W_];
__device__ float g_a[B_ * W_];
__device__ float g_e[B_ * W_];
__device__ float g_alpha[B_];
__device__ float g_gamma[B_];
__device__ float g_sim[B_ * N_];
__device__ float g_partv[B_ * 8 * 4];
__device__ int   g_parti[B_ * 8 * 4];
__device__ int   g_idx4[B_ * 4];
__device__ float g_p4[B_ * 4];
__device__ unsigned long long g_lrukey[B_];

__device__ __forceinline__ float sigmoidf_(float x) { return 1.0f / (1.0f + expf(-x)); }

// ---------------------------------------------------------------------------
// K1: z partials. grid = 32 j-tiles x 8 k-splits = 256 blocks, 256 threads.
// Each block: 64b x 64j tile over 136 k. Thread: 4b x 4j micro-tile.
// ---------------------------------------------------------------------------
__global__ void k_gemm_z(const float* __restrict__ inp, const float* __restrict__ rprev,
                         const float* __restrict__ hprev, const float* __restrict__ Wk,
                         const float* __restrict__ Uk) {
    __shared__ __align__(16) float Xs[8][64];
    __shared__ __align__(16) float Ws[8][64];
    const int jt = blockIdx.x & 31;
    const int ks = blockIdx.x >> 5;
    const int j0 = jt * 64;
    const int kbase = ks * KPER_;
    const int t = threadIdx.x;
    const int tj = t & 15;       // j group
    const int tb = t >> 4;       // b group

    float acc[4][4];
#pragma unroll
    for (int r = 0; r < 4; r++)
#pragma unroll
        for (int c = 0; c < 4; c++) acc[r][c] = 0.0f;

    for (int cch = 0; cch < 17; cch++) {
        const int k0 = kbase + cch * 8;
        // load X: idx -> b=idx>>3, kk=idx&7
        for (int idx = t; idx < 512; idx += 256) {
            int b = idx >> 3, kk = idx & 7, kg = k0 + kk;
            float v;
            if (kg < DIN_)            v = inp[b * DIN_ + kg];
            else if (kg < DIN_ + W_)  v = rprev[b * W_ + (kg - DIN_)];
            else                      v = hprev[b * H_ + (kg - DIN_ - W_)];
            Xs[kk][b] = v;
        }
        // load W: idx -> kk=idx>>6, jj=idx&63
        for (int idx = t; idx < 512; idx += 256) {
            int kk = idx >> 6, jj = idx & 63, kg = k0 + kk;
            float w = (kg < DIN_ + W_) ? Wk[kg * G4_ + j0 + jj]
                                       : Uk[(kg - DIN_ - W_) * G4_ + j0 + jj];
            Ws[kk][jj] = w;
        }
        __syncthreads();
#pragma unroll
        for (int kk = 0; kk < 8; kk++) {
            float4 xv = *(const float4*)&Xs[kk][tb * 4];
            float4 wv = *(const float4*)&Ws[kk][tj * 4];
            float xr[4] = {xv.x, xv.y, xv.z, xv.w};
            float wc[4] = {wv.x, wv.y, wv.z, wv.w};
#pragma unroll
            for (int r = 0; r < 4; r++)
#pragma unroll
                for (int c = 0; c < 4; c++) acc[r][c] += xr[r] * wc[c];
        }
        __syncthreads();
    }
#pragma unroll
    for (int r = 0; r < 4; r++) {
        float4 st = make_float4(acc[r][0], acc[r][1], acc[r][2], acc[r][3]);
        *(float4*)&g_zp[ks * (B_ * G4_) + (tb * 4 + r) * G4_ + j0 + tj * 4] = st;
    }
}

// ---------------------------------------------------------------------------
// K2: reduce partials + gates
// ---------------------------------------------------------------------------
__global__ void k_gates(const float* __restrict__ cprev, const float* __restrict__ bl,
                        float* __restrict__ h_out, float* __restrict__ c_out) {
    int idx = blockIdx.x * blockDim.x + threadIdx.x;
    if (idx >= B_ * H_) return;
    int b = idx >> 9, hh = idx & 511;
    float z[4];
#pragma unroll
    for (int g = 0; g < 4; g++) z[g] = bl[g * H_ + hh];
#pragma unroll
    for (int ks = 0; ks < KSPLIT_; ks++) {
        const float* zp = g_zp + ks * (B_ * G4_) + b * G4_;
#pragma unroll
        for (int g = 0; g < 4; g++) z[g] += zp[g * H_ + hh];
    }
    float ig = sigmoidf_(z[0]);
    float fg = sigmoidf_(z[1]);
    float og = sigmoidf_(z[3]);
    float c  = fg * cprev[idx] + ig * tanhf(z[2]);
    c_out[idx] = c;
    h_out[idx] = og * tanhf(c);
}

// ---------------------------------------------------------------------------
// K3: params = h @ Wp + bp. grid=64 (b), block=256 (j<194). h staged in smem.
// ---------------------------------------------------------------------------
__global__ void k_params(const float* __restrict__ h, const float* __restrict__ Wp,
                         const float* __restrict__ bp) {
    __shared__ float sh[H_];
    const int b = blockIdx.x, j = threadIdx.x;
    for (int k = j; k < H_; k += 256) sh[k] = h[b * H_ + k];
    __syncthreads();
    if (j >= 194) return;
    float acc = bp[j];
    for (int k = 0; k < H_; k++) acc += sh[k] * Wp[k * 194 + j];
    g_params[b * 194 + j] = acc;
}

// ---------------------------------------------------------------------------
// K4: derive qn, a, e, alpha, gamma; zero lru keys
// ---------------------------------------------------------------------------
__global__ void k_derive() {
    int b = blockIdx.x, w = threadIdx.x;
    const float* p = g_params + b * 194;
    float q = p[w];
    float s = q * q;
#pragma unroll
    for (int off = 16; off > 0; off >>= 1) s += __shfl_down_sync(0xffffffffu, s, off);
    __shared__ float ws[2];
    if ((w & 31) == 0) ws[w >> 5] = s;
    __syncthreads();
    float tot = ws[0] + ws[1];
    g_qn[b * W_ + w] = q * rsqrtf(fmaxf(tot, 1e-12f));
    g_a[b * W_ + w]  = p[W_ + w];
    g_e[b * W_ + w]  = sigmoidf_(p[2 * W_ + w]);
    if (w == 0) {
        g_alpha[b] = sigmoidf_(p[192]);
        g_gamma[b] = sigmoidf_(p[193]);
        g_lrukey[b] = 0ULL;
    }
}

// ---------------------------------------------------------------------------
// K5 (FUSED): one pass over M: sim[b,n] AND M_out base update
// (w_w = alpha*gamma*wr_prev for all n; lru row fixed later).
// Warp handles 2 rows: lanes 0-15 row A, 16-31 row B, float4 each.
// grid = B*N/16 = 65536 blocks, block=256.
// ---------------------------------------------------------------------------
__global__ void k_fused(const float* __restrict__ M, const float* __restrict__ wrp,
                        float* __restrict__ Mout) {
    const int b  = blockIdx.x >> 10;
    const int n0 = (blockIdx.x & 1023) << 4;
    const int tid = threadIdx.x;
    __shared__ __align__(16) float se[W_], sa[W_], sq[W_];
    __shared__ float s_ag;
    if (tid < W_) { se[tid] = g_e[b * W_ + tid]; sa[tid] = g_a[b * W_ + tid]; sq[tid] = g_qn[b * W_ + tid]; }
    if (tid == 0) s_ag = g_alpha[b] * g_gamma[b];
    __syncthreads();

    const int lane = tid & 31, warp = tid >> 5;
    const int half = lane >> 4, l16 = lane & 15;
    const int n = n0 + warp * 2 + half;
    const size_t rowoff = ((size_t)b * N_ + n) * W_;

    float4 m = *(const float4*)(M + rowoff + l16 * 4);
    float ww = s_ag * wrp[b * N_ + n];
    float4 e4 = *(const float4*)(se + l16 * 4);
    float4 a4 = *(const float4*)(sa + l16 * 4);
    float4 q4 = *(const float4*)(sq + l16 * 4);

    float dot = m.x * q4.x + m.y * q4.y + m.z * q4.z + m.w * q4.w;
    float ss  = m.x * m.x + m.y * m.y + m.z * m.z + m.w * m.w;
#pragma unroll
    for (int off = 8; off > 0; off >>= 1) {
        dot += __shfl_down_sync(0xffffffffu, dot, off);
        ss  += __shfl_down_sync(0xffffffffu, ss,  off);
    }

    float4 o;
    o.x = m.x * (1.0f - ww * e4.x) + ww * a4.x;
    o.y = m.y * (1.0f - ww * e4.y) + ww * a4.y;
    o.z = m.z * (1.0f - ww * e4.z) + ww * a4.z;
    o.w = m.w * (1.0f - ww * e4.w) + ww * a4.w;
    *(float4*)(Mout + rowoff + l16 * 4) = o;

    if (l16 == 0) g_sim[b * N_ + n] = dot * rsqrtf(fmaxf(ss, 1e-12f));
}

// ---------------------------------------------------------------------------
// K6a: partial top-4 per (b, chunk of 2048). grid=512, block=256
// ---------------------------------------------------------------------------
__global__ void k_top1() {
    const int b = blockIdx.x >> 3, chunk = blockIdx.x & 7;
    const int tid = threadIdx.x;
    __shared__ float sv[256][4];
    __shared__ int   si[256][4];

    float lv[4]; int li[4];
#pragma unroll
    for (int j = 0; j < 4; j++) { lv[j] = -FLT_MAX; li[j] = 0x7FFFFFFF; }
    const float* simb = g_sim + b * N_ + chunk * 2048;
    const int nbase = chunk * 2048;
    for (int i = 0; i < 8; i++) {
        int nl = tid + i * 256;
        float v = simb[nl];
        int n = nbase + nl;
        if (v > lv[3]) {
            lv[3] = v; li[3] = n;
#pragma unroll
            for (int p = 3; p > 0; p--) {
                bool up = (lv[p] > lv[p-1]) || (lv[p] == lv[p-1] && li[p] < li[p-1]);
                if (up) {
                    float tv = lv[p]; lv[p] = lv[p-1]; lv[p-1] = tv;
                    int   ti = li[p]; li[p] = li[p-1]; li[p-1] = ti;
                }
            }
        }
    }
#pragma unroll
    for (int j = 0; j < 4; j++) { sv[tid][j] = lv[j]; si[tid][j] = li[j]; }
    __syncthreads();
    for (int s = 128; s > 0; s >>= 1) {
        if (tid < s) {
            float av[4], bv[4], ov[4]; int ai[4], bi2[4], oi[4];
#pragma unroll
            for (int j = 0; j < 4; j++) {
                av[j] = sv[tid][j];     ai[j]  = si[tid][j];
                bv[j] = sv[tid + s][j]; bi2[j] = si[tid + s][j];
            }
            int pa = 0, pb = 0;
#pragma unroll
            for (int tt = 0; tt < 4; tt++) {
                bool ta = (av[pa] > bv[pb]) || (av[pa] == bv[pb] && ai[pa] < bi2[pb]);
                if (ta) { ov[tt] = av[pa]; oi[tt] = ai[pa]; pa++; }
                else    { ov[tt] = bv[pb]; oi[tt] = bi2[pb]; pb++; }
            }
#pragma unroll
            for (int j = 0; j < 4; j++) { sv[tid][j] = ov[j]; si[tid][j] = oi[j]; }
        }
        __syncthreads();
    }
    if (tid == 0) {
#pragma unroll
        for (int j = 0; j < 4; j++) {
            g_partv[(b * 8 + chunk) * 4 + j] = sv[0][j];
            g_parti[(b * 8 + chunk) * 4 + j] = si[0][j];
        }
    }
}

// ---------------------------------------------------------------------------
// K6b: merge partials -> global top4 + softmax + r_curr. grid=64, block=64
// ---------------------------------------------------------------------------
__global__ void k_top2(const float* __restrict__ Mprev, float* __restrict__ r_out) {
    const int b = blockIdx.x, tid = threadIdx.x;
    __shared__ int s_idx[4];
    __shared__ float s_p[4];
    if (tid == 0) {
        float lv[4]; int li[4];
#pragma unroll
        for (int j = 0; j < 4; j++) { lv[j] = -FLT_MAX; li[j] = 0x7FFFFFFF; }
        for (int c = 0; c < 32; c++) {
            float v = g_partv[b * 32 + c];
            int   n = g_parti[b * 32 + c];
            if (v > lv[3] || (v == lv[3] && n < li[3])) {
                lv[3] = v; li[3] = n;
#pragma unroll
                for (int p = 3; p > 0; p--) {
                    bool up = (lv[p] > lv[p-1]) || (lv[p] == lv[p-1] && li[p] < li[p-1]);
                    if (up) {
                        float tv = lv[p]; lv[p] = lv[p-1]; lv[p-1] = tv;
                        int   ti = li[p]; li[p] = li[p-1]; li[p-1] = ti;
                    }
                }
            }
        }
        float vmax = lv[0], sum = 0.0f, ev[4];
#pragma unroll
        for (int j = 0; j < 4; j++) { ev[j] = expf(lv[j] - vmax); sum += ev[j]; }
        float inv = 1.0f / sum;
#pragma unroll
        for (int j = 0; j < 4; j++) {
            s_p[j] = ev[j] * inv; s_idx[j] = li[j];
            g_p4[b * 4 + j] = s_p[j]; g_idx4[b * 4 + j] = li[j];
        }
    }
    __syncthreads();
    float r = s_p[0] * Mprev[((size_t)b * N_ + s_idx[0]) * W_ + tid]
            + s_p[1] * Mprev[((size_t)b * N_ + s_idx[1]) * W_ + tid]
            + s_p[2] * Mprev[((size_t)b * N_ + s_idx[2]) * W_ + tid]
            + s_p[3] * Mprev[((size_t)b * N_ + s_idx[3]) * W_ + tid];
    r_out[b * W_ + tid] = r;
}

// ---------------------------------------------------------------------------
// K7: write w_r + usage_curr; atomic LRU argmax (packed key). grid=1024, block=256
// ---------------------------------------------------------------------------
__global__ void k_usage(const float* __restrict__ usprev,
                        float* __restrict__ wr_out, float* __restrict__ us_out) {
    const int b = blockIdx.x >> 4, chunk = blockIdx.x & 15;
    const int tid = threadIdx.x;
    const int n0 = chunk * 1024 + tid * 4;
    const int i0 = g_idx4[b * 4 + 0], i1 = g_idx4[b * 4 + 1];
    const int i2 = g_idx4[b * 4 + 2], i3 = g_idx4[b * 4 + 3];
    const float p0 = g_p4[b * 4 + 0], p1 = g_p4[b * 4 + 1];
    const float p2 = g_p4[b * 4 + 2], p3 = g_p4[b * 4 + 3];

    float4 up = *(const float4*)(usprev + b * N_ + n0);
    float uin[4] = {up.x, up.y, up.z, up.w};
    float wr[4], us[4];
    float bm = -1.0f; int bi = 0x7FFFFFFF;
#pragma unroll
    for (int j = 0; j < 4; j++) {
        int n = n0 + j;
        float w = 0.0f; bool hit = false;
        if (n == i0) { w = p0; hit = true; }
        if (n == i1) { w = p1; hit = true; }
        if (n == i2) { w = p2; hit = true; }
        if (n == i3) { w = p3; hit = true; }
        wr[j] = w;
        float u = hit ? 0.0f : uin[j] + 1.0f;
        us[j] = u;
        if (u > bm || (u == bm && n < bi)) { bm = u; bi = n; }
    }
    *(float4*)(wr_out + b * N_ + n0) = make_float4(wr[0], wr[1], wr[2], wr[3]);
    *(float4*)(us_out + b * N_ + n0) = make_float4(us[0], us[1], us[2], us[3]);

    // block reduce (value desc, index asc)
    __shared__ float rv[256];
    __shared__ int   ri[256];
    rv[tid] = bm; ri[tid] = bi;
    __syncthreads();
    for (int s = 128; s > 0; s >>= 1) {
        if (tid < s) {
            float ov = rv[tid + s]; int oi = ri[tid + s];
            if (ov > rv[tid] || (ov == rv[tid] && oi < ri[tid])) { rv[tid] = ov; ri[tid] = oi; }
        }
        __syncthreads();
    }
    if (tid == 0) {
        unsigned long long key = ((unsigned long long)__float_as_uint(rv[0]) << 32)
                               | (unsigned long long)(0xFFFFFFFFu - (unsigned)ri[0]);
        atomicMax(&g_lrukey[b], key);
    }
}

// ---------------------------------------------------------------------------
// K8: fix the single LRU row per batch. grid=64, block=16
// ---------------------------------------------------------------------------
__global__ void k_lrufix(const float* __restrict__ Mprev, const float* __restrict__ wrp,
                         float* __restrict__ Mout) {
    const int b = blockIdx.x, tid = threadIdx.x;
    const unsigned lru = 0xFFFFFFFFu - (unsigned)(g_lrukey[b] & 0xFFFFFFFFULL);
    const float alpha = g_alpha[b], gamma = g_gamma[b];
    const float ww = alpha * (gamma * wrp[b * N_ + lru] + (1.0f - gamma));
    const size_t rowoff = ((size_t)b * N_ + lru) * W_;
    float4 m  = *(const float4*)(Mprev + rowoff + tid * 4);
    float4 e4 = *(const float4*)(g_e + b * W_ + tid * 4);
    float4 a4 = *(const float4*)(g_a + b * W_ + tid * 4);
    float4 o;
    o.x = m.x * (1.0f - ww * e4.x) + ww * a4.x;
    o.y = m.y * (1.0f - ww * e4.y) + ww * a4.y;
    o.z = m.z * (1.0f - ww * e4.z) + ww * a4.z;
    o.w = m.w * (1.0f - ww * e4.w) + ww * a4.w;
    *(float4*)(Mout + rowoff + tid * 4) = o;
}

// ---------------------------------------------------------------------------
// K9: y_out = [h, r] @ Wf + bf. grid=32 (2 b per block), block=512 (j)
// ---------------------------------------------------------------------------
__global__ void k_yout(const float* __restrict__ h, const float* __restrict__ r,
                       const float* __restrict__ Wf, const float* __restrict__ bf,
                       float* __restrict__ y) {
    __shared__ float xs0[H_ + W_], xs1[H_ + W_];
    const int b0 = blockIdx.x * 2;
    const int j = threadIdx.x;
    xs0[j] = h[b0 * H_ + j];
    xs1[j] = h[(b0 + 1) * H_ + j];
    if (j < W_) {
        xs0[H_ + j] = r[b0 * W_ + j];
        xs1[H_ + j] = r[(b0 + 1) * W_ + j];
    }
    __syncthreads();
    float a0 = bf[j], a1 = a0;
    for (int k = 0; k < H_ + W_; k++) {
        float wf = Wf[k * H_ + j];
        a0 += xs0[k] * wf;
        a1 += xs1[k] * wf;
    }
    y[b0 * H_ + j] = a0;
    y[(b0 + 1) * H_ + j] = a1;
}

// ---------------------------------------------------------------------------
extern "C" void kernel_launch(void* const* d_in, const int* in_sizes, int n_in,
                              void* d_out, int out_size) {
    const float* inputs = (const float*)d_in[0];
    const float* h_prev = (const float*)d_in[1];
    const float* c_prev = (const float*)d_in[2];
    const float* M_prev = (const float*)d_in[3];
    const float* wr_prev = (const float*)d_in[4];
    const float* usage_prev = (const float*)d_in[5];
    const float* r_prev = (const float*)d_in[6];
    const float* Wk = (const float*)d_in[7];
    const float* Uk = (const float*)d_in[8];
    const float* b_lstm = (const float*)d_in[9];
    const float* Wp = (const float*)d_in[10];
    const float* bp = (const float*)d_in[11];
    const float* Wf = (const float*)d_in[12];
    const float* bf = (const float*)d_in[13];

    float* out = (float*)d_out;
    float* o_y  = out + OFF_Y;
    float* o_h  = out + OFF_H;
    float* o_c  = out + OFF_C;
    float* o_M  = out + OFF_M;
    float* o_wr = out + OFF_WR;
    float* o_us = out + OFF_US;
    float* o_r  = out + OFF_R;

    k_gemm_z<<<256, 256>>>(inputs, r_prev, h_prev, Wk, Uk);
    k_gates<<<128, 256>>>(c_prev, b_lstm, o_h, o_c);
    k_params<<<64, 256>>>(o_h, Wp, bp);
    k_derive<<<64, 64>>>();
    k_fused<<<65536, 256>>>(M_prev, wr_prev, o_M);
    k_top1<<<512, 256>>>();
    k_top2<<<64, 64>>>(M_prev, o_r);
    k_usage<<<1024, 256>>>(usage_prev, o_wr, o_us);
    k_lrufix<<<64, 16>>>(M_prev, wr_prev, o_M);
    k_yout<<<32, 512>>>(o_h, o_r, Wf, bf, o_y);
}

// round 3
// speedup vs baseline: 3.6519x; 1.3239x over previous
#include <cuda_runtime.h>
#include <cuda_bf16.h>
#include <cstdint>
#include <cfloat>

#define B_    64
#define H_    512
#define N_    16384
#define K_    4
#define W_    64
#define DIN_  512
#define KDIM_ 1088
#define G4_   2048
#define KSPLIT_ 8
#define KPER_   136   // 1088/8

// d_out layout (floats)
#define OFF_Y   0
#define OFF_H   32768
#define OFF_C   65536
#define OFF_M   98304
#define OFF_WR  67207168
#define OFF_US  68255744
#define OFF_R   69304320

// scratch
__device__ float g_zp[KSPLIT_ * B_ * G4_];
__device__ float g_qn[B_ * W_];
__device__ float g_a[B_ * W_];
__device__ float g_e[B_ * W_];
__device__ float g_alpha[B_];
__device__ float g_gamma[B_];
__device__ float g_sim[B_ * N_];
__device__ float g_partv[B_ * 8 * 4];
__device__ int   g_parti[B_ * 8 * 4];
__device__ int   g_idx4[B_ * 4];
__device__ float g_p4[B_ * 4];
__device__ unsigned long long g_lrukey[B_];

__device__ __forceinline__ float sigmoidf_(float x) { return 1.0f / (1.0f + expf(-x)); }

// ---------------------------------------------------------------------------
// K1: z partials. grid = 32 j-tiles x 8 k-splits, 256 threads.
// ---------------------------------------------------------------------------
__global__ void k_gemm_z(const float* __restrict__ inp, const float* __restrict__ rprev,
                         const float* __restrict__ hprev, const float* __restrict__ Wk,
                         const float* __restrict__ Uk) {
    __shared__ __align__(16) float Xs[8][64];
    __shared__ __align__(16) float Ws[8][64];
    const int jt = blockIdx.x & 31;
    const int ks = blockIdx.x >> 5;
    const int j0 = jt * 64;
    const int kbase = ks * KPER_;
    const int t = threadIdx.x;
    const int tj = t & 15;
    const int tb = t >> 4;

    float acc[4][4];
#pragma unroll
    for (int r = 0; r < 4; r++)
#pragma unroll
        for (int c = 0; c < 4; c++) acc[r][c] = 0.0f;

    for (int cch = 0; cch < 17; cch++) {
        const int k0 = kbase + cch * 8;
        for (int idx = t; idx < 512; idx += 256) {
            int b = idx >> 3, kk = idx & 7, kg = k0 + kk;
            float v;
            if (kg < DIN_)            v = inp[b * DIN_ + kg];
            else if (kg < DIN_ + W_)  v = rprev[b * W_ + (kg - DIN_)];
            else                      v = hprev[b * H_ + (kg - DIN_ - W_)];
            Xs[kk][b] = v;
        }
        for (int idx = t; idx < 512; idx += 256) {
            int kk = idx >> 6, jj = idx & 63, kg = k0 + kk;
            float w = (kg < DIN_ + W_) ? Wk[kg * G4_ + j0 + jj]
                                       : Uk[(kg - DIN_ - W_) * G4_ + j0 + jj];
            Ws[kk][jj] = w;
        }
        __syncthreads();
#pragma unroll
        for (int kk = 0; kk < 8; kk++) {
            float4 xv = *(const float4*)&Xs[kk][tb * 4];
            float4 wv = *(const float4*)&Ws[kk][tj * 4];
            float xr[4] = {xv.x, xv.y, xv.z, xv.w};
            float wc[4] = {wv.x, wv.y, wv.z, wv.w};
#pragma unroll
            for (int r = 0; r < 4; r++)
#pragma unroll
                for (int c = 0; c < 4; c++) acc[r][c] += xr[r] * wc[c];
        }
        __syncthreads();
    }
#pragma unroll
    for (int r = 0; r < 4; r++) {
        float4 st = make_float4(acc[r][0], acc[r][1], acc[r][2], acc[r][3]);
        *(float4*)&g_zp[ks * (B_ * G4_) + (tb * 4 + r) * G4_ + j0 + tj * 4] = st;
    }
}

// ---------------------------------------------------------------------------
// K2: reduce partials + gates
// ---------------------------------------------------------------------------
__global__ void k_gates(const float* __restrict__ cprev, const float* __restrict__ bl,
                        float* __restrict__ h_out, float* __restrict__ c_out) {
    int idx = blockIdx.x * blockDim.x + threadIdx.x;
    if (idx >= B_ * H_) return;
    int b = idx >> 9, hh = idx & 511;
    float z[4];
#pragma unroll
    for (int g = 0; g < 4; g++) z[g] = bl[g * H_ + hh];
#pragma unroll
    for (int ks = 0; ks < KSPLIT_; ks++) {
        const float* zp = g_zp + ks * (B_ * G4_) + b * G4_;
#pragma unroll
        for (int g = 0; g < 4; g++) z[g] += zp[g * H_ + hh];
    }
    float ig = sigmoidf_(z[0]);
    float fg = sigmoidf_(z[1]);
    float og = sigmoidf_(z[3]);
    float c  = fg * cprev[idx] + ig * tanhf(z[2]);
    c_out[idx] = c;
    h_out[idx] = og * tanhf(c);
}

// ---------------------------------------------------------------------------
// K3 (merged params + derive): grid=64 (b), block=256
// ---------------------------------------------------------------------------
__global__ void k_params_derive(const float* __restrict__ h, const float* __restrict__ Wp,
                                const float* __restrict__ bp) {
    __shared__ float sh[H_];
    __shared__ float sp[194];
    __shared__ float ws[2];
    const int b = blockIdx.x, j = threadIdx.x;
    for (int k = j; k < H_; k += 256) sh[k] = h[b * H_ + k];
    __syncthreads();
    if (j < 194) {
        float acc = bp[j];
        for (int k = 0; k < H_; k++) acc += sh[k] * Wp[k * 194 + j];
        sp[j] = acc;
    }
    __syncthreads();
    if (j < 64) {
        float q = sp[j];
        float s = q * q;
#pragma unroll
        for (int off = 16; off > 0; off >>= 1) s += __shfl_down_sync(0xffffffffu, s, off);
        if ((j & 31) == 0) ws[j >> 5] = s;
    }
    __syncthreads();
    if (j < 64) {
        float tot = ws[0] + ws[1];
        g_qn[b * W_ + j] = sp[j] * rsqrtf(fmaxf(tot, 1e-12f));
        g_a[b * W_ + j]  = sp[W_ + j];
        g_e[b * W_ + j]  = sigmoidf_(sp[2 * W_ + j]);
        if (j == 0) {
            g_alpha[b] = sigmoidf_(sp[192]);
            g_gamma[b] = sigmoidf_(sp[193]);
            g_lrukey[b] = 0ULL;
        }
    }
}

// ---------------------------------------------------------------------------
// K4 (FUSED, MLP=8): one pass over M: sim + base M update.
// grid = B*N/128 = 8192 blocks, block = 256 (8 warps).
// Warp w, iter i, half h -> local row i*16 + w*2 + h (i=0..7).
// ---------------------------------------------------------------------------
__global__ void k_fused(const float* __restrict__ M, const float* __restrict__ wrp,
                        float* __restrict__ Mout) {
    const int b  = blockIdx.x >> 7;
    const int n0 = (blockIdx.x & 127) << 7;   // 128 rows per block
    const int tid = threadIdx.x;
    __shared__ __align__(16) float se[W_], sa[W_], sq[W_];
    __shared__ float s_sim[128];
    __shared__ float s_ag;
    if (tid < W_) { se[tid] = g_e[b * W_ + tid]; sa[tid] = g_a[b * W_ + tid]; sq[tid] = g_qn[b * W_ + tid]; }
    if (tid == 0) s_ag = g_alpha[b] * g_gamma[b];
    __syncthreads();

    const int lane = tid & 31, warp = tid >> 5;
    const int half = lane >> 4, l16 = lane & 15;
    const int rbase = warp * 2 + half;          // local row for i=0

    const size_t browoff = (size_t)b * N_ + n0;

    // front-batched loads (MLP_p1 = 8 for M + 8 for wr)
    float4 m[8];
    float wr[8];
#pragma unroll
    for (int i = 0; i < 8; i++) {
        const int nl = i * 16 + rbase;
        m[i] = __ldcs((const float4*)(M + (browoff + nl) * W_) + l16);
    }
#pragma unroll
    for (int i = 0; i < 8; i++) {
        const int nl = i * 16 + rbase;
        wr[i] = __ldg(wrp + browoff + nl);
    }

    const float4 e4 = *(const float4*)(se + l16 * 4);
    const float4 a4 = *(const float4*)(sa + l16 * 4);
    const float4 q4 = *(const float4*)(sq + l16 * 4);
    const float ag = s_ag;

#pragma unroll
    for (int i = 0; i < 8; i++) {
        float dot = m[i].x * q4.x + m[i].y * q4.y + m[i].z * q4.z + m[i].w * q4.w;
        float ss  = m[i].x * m[i].x + m[i].y * m[i].y + m[i].z * m[i].z + m[i].w * m[i].w;
#pragma unroll
        for (int off = 8; off > 0; off >>= 1) {
            dot += __shfl_down_sync(0xffffffffu, dot, off);
            ss  += __shfl_down_sync(0xffffffffu, ss,  off);
        }
        if (l16 == 0) s_sim[i * 16 + rbase] = dot * rsqrtf(fmaxf(ss, 1e-12f));

        const float ww = ag * wr[i];
        float4 o;
        o.x = m[i].x * (1.0f - ww * e4.x) + ww * a4.x;
        o.y = m[i].y * (1.0f - ww * e4.y) + ww * a4.y;
        o.z = m[i].z * (1.0f - ww * e4.z) + ww * a4.z;
        o.w = m[i].w * (1.0f - ww * e4.w) + ww * a4.w;
        const int nl = i * 16 + rbase;
        __stcs((float4*)(Mout + (browoff + nl) * W_) + l16, o);
    }
    __syncthreads();
    if (tid < 128) g_sim[browoff + tid] = s_sim[tid];
}

// ---------------------------------------------------------------------------
// K5a: partial top-4 per (b, chunk of 2048). grid=512, block=256
// ---------------------------------------------------------------------------
__global__ void k_top1() {
    const int b = blockIdx.x >> 3, chunk = blockIdx.x & 7;
    const int tid = threadIdx.x;
    __shared__ float sv[256][4];
    __shared__ int   si[256][4];

    float lv[4]; int li[4];
#pragma unroll
    for (int j = 0; j < 4; j++) { lv[j] = -FLT_MAX; li[j] = 0x7FFFFFFF; }
    const float* simb = g_sim + b * N_ + chunk * 2048;
    const int nbase = chunk * 2048;
    for (int i = 0; i < 8; i++) {
        int nl = tid + i * 256;
        float v = simb[nl];
        int n = nbase + nl;
        if (v > lv[3]) {
            lv[3] = v; li[3] = n;
#pragma unroll
            for (int p = 3; p > 0; p--) {
                bool up = (lv[p] > lv[p-1]) || (lv[p] == lv[p-1] && li[p] < li[p-1]);
                if (up) {
                    float tv = lv[p]; lv[p] = lv[p-1]; lv[p-1] = tv;
                    int   ti = li[p]; li[p] = li[p-1]; li[p-1] = ti;
                }
            }
        }
    }
#pragma unroll
    for (int j = 0; j < 4; j++) { sv[tid][j] = lv[j]; si[tid][j] = li[j]; }
    __syncthreads();
    for (int s = 128; s > 0; s >>= 1) {
        if (tid < s) {
            float av[4], bv[4], ov[4]; int ai[4], bi2[4], oi[4];
#pragma unroll
            for (int j = 0; j < 4; j++) {
                av[j] = sv[tid][j];     ai[j]  = si[tid][j];
                bv[j] = sv[tid + s][j]; bi2[j] = si[tid + s][j];
            }
            int pa = 0, pb = 0;
#pragma unroll
            for (int tt = 0; tt < 4; tt++) {
                bool ta = (av[pa] > bv[pb]) || (av[pa] == bv[pb] && ai[pa] < bi2[pb]);
                if (ta) { ov[tt] = av[pa]; oi[tt] = ai[pa]; pa++; }
                else    { ov[tt] = bv[pb]; oi[tt] = bi2[pb]; pb++; }
            }
#pragma unroll
            for (int j = 0; j < 4; j++) { sv[tid][j] = ov[j]; si[tid][j] = oi[j]; }
        }
        __syncthreads();
    }
    if (tid == 0) {
#pragma unroll
        for (int j = 0; j < 4; j++) {
            g_partv[(b * 8 + chunk) * 4 + j] = sv[0][j];
            g_parti[(b * 8 + chunk) * 4 + j] = si[0][j];
        }
    }
}

// ---------------------------------------------------------------------------
// K5b: merge partials -> global top4 + softmax + r_curr. grid=64, block=64
// ---------------------------------------------------------------------------
__global__ void k_top2(const float* __restrict__ Mprev, float* __restrict__ r_out) {
    const int b = blockIdx.x, tid = threadIdx.x;
    __shared__ int s_idx[4];
    __shared__ float s_p[4];
    if (tid == 0) {
        float lv[4]; int li[4];
#pragma unroll
        for (int j = 0; j < 4; j++) { lv[j] = -FLT_MAX; li[j] = 0x7FFFFFFF; }
        for (int c = 0; c < 32; c++) {
            float v = g_partv[b * 32 + c];
            int   n = g_parti[b * 32 + c];
            if (v > lv[3] || (v == lv[3] && n < li[3])) {
                lv[3] = v; li[3] = n;
#pragma unroll
                for (int p = 3; p > 0; p--) {
                    bool up = (lv[p] > lv[p-1]) || (lv[p] == lv[p-1] && li[p] < li[p-1]);
                    if (up) {
                        float tv = lv[p]; lv[p] = lv[p-1]; lv[p-1] = tv;
                        int   ti = li[p]; li[p] = li[p-1]; li[p-1] = ti;
                    }
                }
            }
        }
        float vmax = lv[0], sum = 0.0f, ev[4];
#pragma unroll
        for (int j = 0; j < 4; j++) { ev[j] = expf(lv[j] - vmax); sum += ev[j]; }
        float inv = 1.0f / sum;
#pragma unroll
        for (int j = 0; j < 4; j++) {
            s_p[j] = ev[j] * inv; s_idx[j] = li[j];
            g_p4[b * 4 + j] = s_p[j]; g_idx4[b * 4 + j] = li[j];
        }
    }
    __syncthreads();
    float r = s_p[0] * Mprev[((size_t)b * N_ + s_idx[0]) * W_ + tid]
            + s_p[1] * Mprev[((size_t)b * N_ + s_idx[1]) * W_ + tid]
            + s_p[2] * Mprev[((size_t)b * N_ + s_idx[2]) * W_ + tid]
            + s_p[3] * Mprev[((size_t)b * N_ + s_idx[3]) * W_ + tid];
    r_out[b * W_ + tid] = r;
}

// ---------------------------------------------------------------------------
// K6: w_r + usage_curr; atomic LRU argmax. grid=1024, block=256
// ---------------------------------------------------------------------------
__global__ void k_usage(const float* __restrict__ usprev,
                        float* __restrict__ wr_out, float* __restrict__ us_out) {
    const int b = blockIdx.x >> 4, chunk = blockIdx.x & 15;
    const int tid = threadIdx.x;
    const int n0 = chunk * 1024 + tid * 4;
    const int i0 = g_idx4[b * 4 + 0], i1 = g_idx4[b * 4 + 1];
    const int i2 = g_idx4[b * 4 + 2], i3 = g_idx4[b * 4 + 3];
    const float p0 = g_p4[b * 4 + 0], p1 = g_p4[b * 4 + 1];
    const float p2 = g_p4[b * 4 + 2], p3 = g_p4[b * 4 + 3];

    float4 up = *(const float4*)(usprev + b * N_ + n0);
    float uin[4] = {up.x, up.y, up.z, up.w};
    float wr[4], us[4];
    float bm = -1.0f; int bi = 0x7FFFFFFF;
#pragma unroll
    for (int j = 0; j < 4; j++) {
        int n = n0 + j;
        float w = 0.0f; bool hit = false;
        if (n == i0) { w = p0; hit = true; }
        if (n == i1) { w = p1; hit = true; }
        if (n == i2) { w = p2; hit = true; }
        if (n == i3) { w = p3; hit = true; }
        wr[j] = w;
        float u = hit ? 0.0f : uin[j] + 1.0f;
        us[j] = u;
        if (u > bm || (u == bm && n < bi)) { bm = u; bi = n; }
    }
    *(float4*)(wr_out + b * N_ + n0) = make_float4(wr[0], wr[1], wr[2], wr[3]);
    *(float4*)(us_out + b * N_ + n0) = make_float4(us[0], us[1], us[2], us[3]);

    __shared__ float rv[256];
    __shared__ int   ri[256];
    rv[tid] = bm; ri[tid] = bi;
    __syncthreads();
    for (int s = 128; s > 0; s >>= 1) {
        if (tid < s) {
            float ov = rv[tid + s]; int oi = ri[tid + s];
            if (ov > rv[tid] || (ov == rv[tid] && oi < ri[tid])) { rv[tid] = ov; ri[tid] = oi; }
        }
        __syncthreads();
    }
    if (tid == 0) {
        unsigned long long key = ((unsigned long long)__float_as_uint(rv[0]) << 32)
                               | (unsigned long long)(0xFFFFFFFFu - (unsigned)ri[0]);
        atomicMax(&g_lrukey[b], key);
    }
}

// ---------------------------------------------------------------------------
// K7: fix the single LRU row per batch. grid=64, block=16
// ---------------------------------------------------------------------------
__global__ void k_lrufix(const float* __restrict__ Mprev, const float* __restrict__ wrp,
                         float* __restrict__ Mout) {
    const int b = blockIdx.x, tid = threadIdx.x;
    const unsigned lru = 0xFFFFFFFFu - (unsigned)(g_lrukey[b] & 0xFFFFFFFFULL);
    const float alpha = g_alpha[b], gamma = g_gamma[b];
    const float ww = alpha * (gamma * wrp[b * N_ + lru] + (1.0f - gamma));
    const size_t rowoff = ((size_t)b * N_ + lru) * W_;
    float4 m  = *(const float4*)(Mprev + rowoff + tid * 4);
    float4 e4 = *(const float4*)(g_e + b * W_ + tid * 4);
    float4 a4 = *(const float4*)(g_a + b * W_ + tid * 4);
    float4 o;
    o.x = m.x * (1.0f - ww * e4.x) + ww * a4.x;
    o.y = m.y * (1.0f - ww * e4.y) + ww * a4.y;
    o.z = m.z * (1.0f - ww * e4.z) + ww * a4.z;
    o.w = m.w * (1.0f - ww * e4.w) + ww * a4.w;
    *(float4*)(Mout + rowoff + tid * 4) = o;
}

// ---------------------------------------------------------------------------
// K8: y_out = [h, r] @ Wf + bf. grid=32 (2 b per block), block=512 (j)
// ---------------------------------------------------------------------------
__global__ void k_yout(const float* __restrict__ h, const float* __restrict__ r,
                       const float* __restrict__ Wf, const float* __restrict__ bf,
                       float* __restrict__ y) {
    __shared__ float xs0[H_ + W_], xs1[H_ + W_];
    const int b0 = blockIdx.x * 2;
    const int j = threadIdx.x;
    xs0[j] = h[b0 * H_ + j];
    xs1[j] = h[(b0 + 1) * H_ + j];
    if (j < W_) {
        xs0[H_ + j] = r[b0 * W_ + j];
        xs1[H_ + j] = r[(b0 + 1) * W_ + j];
    }
    __syncthreads();
    float a0 = bf[j], a1 = a0;
    for (int k = 0; k < H_ + W_; k++) {
        float wf = Wf[k * H_ + j];
        a0 += xs0[k] * wf;
        a1 += xs1[k] * wf;
    }
    y[b0 * H_ + j] = a0;
    y[(b0 + 1) * H_ + j] = a1;
}

// ---------------------------------------------------------------------------
extern "C" void kernel_launch(void* const* d_in, const int* in_sizes, int n_in,
                              void* d_out, int out_size) {
    const float* inputs = (const float*)d_in[0];
    const float* h_prev = (const float*)d_in[1];
    const float* c_prev = (const float*)d_in[2];
    const float* M_prev = (const float*)d_in[3];
    const float* wr_prev = (const float*)d_in[4];
    const float* usage_prev = (const float*)d_in[5];
    const float* r_prev = (const float*)d_in[6];
    const float* Wk = (const float*)d_in[7];
    const float* Uk = (const float*)d_in[8];
    const float* b_lstm = (const float*)d_in[9];
    const float* Wp = (const float*)d_in[10];
    const float* bp = (const float*)d_in[11];
    const float* Wf = (const float*)d_in[12];
    const float* bf = (const float*)d_in[13];

    float* out = (float*)d_out;
    float* o_y  = out + OFF_Y;
    float* o_h  = out + OFF_H;
    float* o_c  = out + OFF_C;
    float* o_M  = out + OFF_M;
    float* o_wr = out + OFF_WR;
    float* o_us = out + OFF_US;
    float* o_r  = out + OFF_R;

    k_gemm_z<<<256, 256>>>(inputs, r_prev, h_prev, Wk, Uk);
    k_gates<<<128, 256>>>(c_prev, b_lstm, o_h, o_c);
    k_params_derive<<<64, 256>>>(o_h, Wp, bp);
    k_fused<<<8192, 256>>>(M_prev, wr_prev, o_M);
    k_top1<<<512, 256>>>();
    k_top2<<<64, 64>>>(M_prev, o_r);
    k_usage<<<1024, 256>>>(usage_prev, o_wr, o_us);
    k_lrufix<<<64, 16>>>(M_prev, wr_prev, o_M);
    k_yout<<<32, 512>>>(o_h, o_r, Wf, bf, o_y);
}